// round 2
// baseline (speedup 1.0000x reference)
#include <cuda_runtime.h>

#define NB     8
#define LQ     4096
#define SK     4096
#define NHEADS 8
#define DD     64
#define MM     64

// Scratch (no allocations allowed): KV[nh][d][m], Ksum[nh][d]
__device__ float g_KV[64 * 64 * 64];
__device__ float g_Ksum[64 * 64];

__device__ __forceinline__ float phi(float x) {
    // elu(x) + 1
    return x > 0.f ? x + 1.f : __expf(x);
}

__global__ void zero_kernel() {
    int i = blockIdx.x * blockDim.x + threadIdx.x;   // grid covers 64*64*64 exactly
    g_KV[i] = 0.f;
    if (i < 64 * 64) g_Ksum[i] = 0.f;
}

// Stage 1: KV[nh][d][m] += phi(k)[d]*v[m], Ksum[nh][d] += phi(k)[d]
// grid (64 nh, 8 s-chunks), 256 threads. Each thread: 4x4 tile of the 64x64 accumulator.
__global__ __launch_bounds__(256) void stage1_kernel(
    const float* __restrict__ Kg, const float* __restrict__ Vg,
    const float* __restrict__ maskg)
{
    const int nh = blockIdx.x;
    const int n = nh >> 3, h = nh & 7;
    const int sc = blockIdx.y;
    const int tid = threadIdx.x;
    const int td = tid & 15;        // d tile: 4*td..4*td+3
    const int tm = tid >> 4;        // m tile: 4*tm..4*tm+3

    __shared__ __align__(16) float ks[8][DD];
    __shared__ __align__(16) float vs[8][MM];

    float acc[4][4] = {};
    float ksum[4] = {0.f, 0.f, 0.f, 0.f};

    const int s0 = sc * (SK / 8);
    const int which = tid >> 7;          // 0: load k tile, 1: load v tile
    const int lr = (tid >> 4) & 7;       // row within 8-row batch
    const int lc = tid & 15;             // float4 column

    for (int sb = 0; sb < SK / 8; sb += 8) {
        const int s = s0 + sb + lr;
        if (which == 0) {
            float4 val = *((const float4*)(Kg + ((n * SK + s) * NHEADS + h) * DD) + lc);
            const float mk = maskg[n * SK + s];
            val.x = phi(val.x) * mk; val.y = phi(val.y) * mk;
            val.z = phi(val.z) * mk; val.w = phi(val.w) * mk;
            ((float4*)&ks[lr][0])[lc] = val;
        } else {
            float4 val = *((const float4*)(Vg + ((n * SK + s) * NHEADS + h) * DD) + lc);
            ((float4*)&vs[lr][0])[lc] = val;
        }
        __syncthreads();
        #pragma unroll
        for (int ss = 0; ss < 8; ss++) {
            const float4 k4 = ((const float4*)&ks[ss][0])[td];
            const float4 v4 = ((const float4*)&vs[ss][0])[tm];
            const float ka[4] = {k4.x, k4.y, k4.z, k4.w};
            const float va[4] = {v4.x, v4.y, v4.z, v4.w};
            #pragma unroll
            for (int i = 0; i < 4; i++)
                #pragma unroll
                for (int j = 0; j < 4; j++)
                    acc[i][j] = fmaf(ka[i], va[j], acc[i][j]);
            if (tm == 0) {
                #pragma unroll
                for (int i = 0; i < 4; i++) ksum[i] += ka[i];
            }
        }
        __syncthreads();
    }

    float* kvbase = &g_KV[(nh * 64 + 4 * td) * 64 + 4 * tm];
    #pragma unroll
    for (int i = 0; i < 4; i++)
        #pragma unroll
        for (int j = 0; j < 4; j++)
            atomicAdd(kvbase + i * 64 + j, acc[i][j]);
    if (tm == 0) {
        #pragma unroll
        for (int i = 0; i < 4; i++)
            atomicAdd(&g_Ksum[nh * 64 + 4 * td + i], ksum[i]);
    }
}

// Stage 2: out[l][m] = (sum_d phi(q)[l][d] * KV[d][m]) * z[l]
// grid (64 l-tiles, 64 nh), 256 threads. Per-block tile: 64 l x 64 m.
#define LTILE   64
#define QSTRIDE 68   // 64 + 4: 16B-aligned rows, conflict-free tiled loads

__global__ __launch_bounds__(256) void stage2_kernel(
    const float* __restrict__ Qg, float* __restrict__ Outg)
{
    const int nh = blockIdx.y;
    const int n = nh >> 3, h = nh & 7;
    const int l0 = blockIdx.x * LTILE;
    const int tid = threadIdx.x;
    const int tm = tid & 15;     // m tile: 4*tm..4*tm+3
    const int tl = tid >> 4;     // l tile: 4*tl..4*tl+3

    __shared__ __align__(16) float Qs[DD][QSTRIDE];   // [d][l]
    __shared__ __align__(16) float KVs[DD][MM];       // [d][m]
    __shared__ float ksums[DD];
    __shared__ float zs[LTILE];

    // Load+transpose Q tile with phi applied
    for (int idx = tid; idx < LTILE * DD; idx += 256) {
        const int l = idx >> 6, d = idx & 63;
        const float q = Qg[((n * LQ + l0 + l) * NHEADS + h) * DD + d];
        Qs[d][l] = phi(q);
    }
    // Load KV tile (L2 resident: 1MB total across all blocks)
    for (int idx = tid; idx < DD * MM / 4; idx += 256)
        ((float4*)KVs)[idx] = ((const float4*)(g_KV + nh * DD * MM))[idx];
    if (tid < DD) ksums[tid] = g_Ksum[nh * DD + tid];
    __syncthreads();

    // z[l] = 1/(phi(q)[l] . Ksum + eps)
    if (tid < LTILE) {
        float a = 0.f;
        #pragma unroll
        for (int d = 0; d < DD; d++) a = fmaf(Qs[d][tid], ksums[d], a);
        zs[tid] = 1.f / (a + 1e-6f);
    }
    __syncthreads();

    float acc[4][4] = {};
    #pragma unroll 8
    for (int d = 0; d < DD; d++) {
        const float4 a = *(const float4*)&Qs[d][4 * tl];
        const float4 b = *(const float4*)&KVs[d][4 * tm];
        const float aa[4] = {a.x, a.y, a.z, a.w};
        const float bb[4] = {b.x, b.y, b.z, b.w};
        #pragma unroll
        for (int i = 0; i < 4; i++)
            #pragma unroll
            for (int j = 0; j < 4; j++)
                acc[i][j] = fmaf(aa[i], bb[j], acc[i][j]);
    }

    #pragma unroll
    for (int i = 0; i < 4; i++) {
        const int l = l0 + 4 * tl + i;
        const float z = zs[4 * tl + i];
        float4 o;
        o.x = acc[i][0] * z; o.y = acc[i][1] * z;
        o.z = acc[i][2] * z; o.w = acc[i][3] * z;
        *(float4*)&Outg[((n * LQ + l) * NHEADS + h) * MM + 4 * tm] = o;
    }
}

extern "C" void kernel_launch(void* const* d_in, const int* in_sizes, int n_in,
                              void* d_out, int out_size)
{
    const float* Q    = (const float*)d_in[0];
    const float* K    = (const float*)d_in[1];
    const float* V    = (const float*)d_in[2];
    const float* mask = (const float*)d_in[3];
    float* Out = (float*)d_out;

    zero_kernel<<<(64 * 64 * 64) / 256, 256>>>();
    stage1_kernel<<<dim3(64, 8), 256>>>(K, V, mask);
    stage2_kernel<<<dim3(LQ / LTILE, 64), 256>>>(Q, Out);
}

// round 3
// speedup vs baseline: 1.1718x; 1.1718x over previous
#include <cuda_runtime.h>

#define LQ 4096
#define SK 4096
#define NH_TOT 64      // N*H = 8*8
#define DD 64
#define MM 64
#define S1_CHUNKS 16
#define S1_ROWS  (SK / S1_CHUNKS)   // 256
#define S1_BATCH 16
#define LTILE 64
#define QSTRIDE 68     // 64+4 floats: 272B rows (16B-aligned), conflict-free

typedef unsigned long long ull;

// Scratch (__device__ globals; no allocation allowed)
__device__ float g_KVp[S1_CHUNKS * NH_TOT * DD * MM];   // per-chunk partial KV
__device__ float g_Ksp[S1_CHUNKS * NH_TOT * DD];        // per-chunk partial Ksum
__device__ float g_KV [NH_TOT * DD * MM];
__device__ float g_Ksum[NH_TOT * DD];

__device__ __forceinline__ float phi(float x) {         // elu(x)+1
    return x > 0.f ? x + 1.f : __expf(x);
}
__device__ __forceinline__ ull pack2(float lo, float hi) {
    ull r; asm("mov.b64 %0, {%1, %2};" : "=l"(r) : "f"(lo), "f"(hi)); return r;
}
__device__ __forceinline__ void ffma2(ull &d, ull a, ull b) {
    asm("fma.rn.f32x2 %0, %1, %2, %0;" : "+l"(d) : "l"(a), "l"(b));
}
__device__ __forceinline__ ull mul2(ull a, ull b) {
    ull d; asm("mul.rn.f32x2 %0, %1, %2;" : "=l"(d) : "l"(a), "l"(b)); return d;
}

union F4U { float4 f; ull u[2]; float s[4]; };

// ───────────────────────── Stage 1 ─────────────────────────
// KV_part[chunk][nh][d][m] = sum_{s in chunk} phi(k)[d]*mask*v[m]
// 128 threads: thread grid 16(d-tiles of 4) x 8(m-tiles of 8), packed f32x2 FMA.
__global__ __launch_bounds__(128) void stage1_kernel(
    const float* __restrict__ Kg, const float* __restrict__ Vg,
    const float* __restrict__ maskg)
{
    const int nh = blockIdx.x, chunk = blockIdx.y;
    const int n = nh >> 3, h = nh & 7;
    const int tid = threadIdx.x;
    const int td = tid & 15;    // d tile: 4*td..4*td+3
    const int tm = tid >> 4;    // m tile: 8*tm..8*tm+7

    __shared__ __align__(16) float ks[S1_BATCH][DD];
    __shared__ __align__(16) float vs[S1_BATCH][MM];

    ull acc[4][4];
    #pragma unroll
    for (int i = 0; i < 4; i++)
        #pragma unroll
        for (int j = 0; j < 4; j++) acc[i][j] = 0ull;
    float ksum[4] = {0.f, 0.f, 0.f, 0.f};

    const int s0 = chunk * S1_ROWS;

    for (int b = 0; b < S1_ROWS; b += S1_BATCH) {
        // Produce 16-row K/V tiles (each thread: 2 K-float4 + 2 V-float4)
        #pragma unroll
        for (int u = 0; u < 2; u++) {
            const int li = tid + 128 * u;        // 0..255
            const int r = li >> 4, c = li & 15;
            const int s = s0 + b + r;
            const int base = ((n * SK + s) * 8 + h) * DD;
            F4U k4; k4.f = *((const float4*)(Kg + base) + c);
            const float mk = maskg[n * SK + s];
            k4.s[0] = phi(k4.s[0]) * mk; k4.s[1] = phi(k4.s[1]) * mk;
            k4.s[2] = phi(k4.s[2]) * mk; k4.s[3] = phi(k4.s[3]) * mk;
            ((float4*)&ks[r][0])[c] = k4.f;
            F4U v4; v4.f = *((const float4*)(Vg + base) + c);
            ((float4*)&vs[r][0])[c] = v4.f;
        }
        __syncthreads();
        #pragma unroll
        for (int r = 0; r < S1_BATCH; r++) {
            F4U k4, va, vb;
            k4.f = ((const float4*)&ks[r][0])[td];
            va.f = ((const float4*)&vs[r][0])[2 * tm];
            vb.f = ((const float4*)&vs[r][0])[2 * tm + 1];
            #pragma unroll
            for (int i = 0; i < 4; i++) {
                const ull ka = pack2(k4.s[i], k4.s[i]);
                ffma2(acc[i][0], ka, va.u[0]);
                ffma2(acc[i][1], ka, va.u[1]);
                ffma2(acc[i][2], ka, vb.u[0]);
                ffma2(acc[i][3], ka, vb.u[1]);
            }
            if (tm == 0) {
                #pragma unroll
                for (int i = 0; i < 4; i++) ksum[i] += k4.s[i];
            }
        }
        __syncthreads();
    }

    // Plain stores to per-chunk partials (no atomics)
    float* dst = g_KVp + ((chunk * NH_TOT + nh) * DD + 4 * td) * MM + 8 * tm;
    #pragma unroll
    for (int i = 0; i < 4; i++) {
        F4U lo, hi;
        lo.u[0] = acc[i][0]; lo.u[1] = acc[i][1];
        hi.u[0] = acc[i][2]; hi.u[1] = acc[i][3];
        *(float4*)(dst + i * MM)     = lo.f;
        *(float4*)(dst + i * MM + 4) = hi.f;
    }
    if (tm == 0) {
        float* kd = g_Ksp + (chunk * NH_TOT + nh) * DD + 4 * td;
        #pragma unroll
        for (int i = 0; i < 4; i++) kd[i] = ksum[i];
    }
}

// ───────────────────────── Reduce partials ─────────────────────────
__global__ __launch_bounds__(256) void reduce_kernel() {
    const int idx = blockIdx.x * 256 + threadIdx.x;
    const int KV4 = NH_TOT * DD * MM / 4;    // 65536
    const int KS4 = NH_TOT * DD / 4;         // 1024
    if (idx < KV4) {
        float4 s = make_float4(0.f, 0.f, 0.f, 0.f);
        #pragma unroll
        for (int c = 0; c < S1_CHUNKS; c++) {
            float4 p = ((const float4*)g_KVp)[c * KV4 + idx];
            s.x += p.x; s.y += p.y; s.z += p.z; s.w += p.w;
        }
        ((float4*)g_KV)[idx] = s;
    } else if (idx < KV4 + KS4) {
        const int j = idx - KV4;
        float4 s = make_float4(0.f, 0.f, 0.f, 0.f);
        #pragma unroll
        for (int c = 0; c < S1_CHUNKS; c++) {
            float4 p = ((const float4*)g_Ksp)[c * KS4 + j];
            s.x += p.x; s.y += p.y; s.z += p.z; s.w += p.w;
        }
        ((float4*)g_Ksum)[j] = s;
    }
}

// ───────────────────────── Stage 2 ─────────────────────────
// out[l][m] = (sum_d phi(q)[l][d] * KV[d][m]) * z[l]
// 128 threads: thread grid 16(l-tiles of 4) x 8(m-tiles of 8), packed f32x2 FMA.
__global__ __launch_bounds__(128) void stage2_kernel(
    const float* __restrict__ Qg, float* __restrict__ Outg)
{
    const int nh = blockIdx.y;
    const int n = nh >> 3, h = nh & 7;
    const int l0 = blockIdx.x * LTILE;
    const int tid = threadIdx.x;
    const int tl = tid >> 3;    // 0..15: l tile of 4
    const int tm = tid & 7;     // 0..7 : m tile of 8

    __shared__ __align__(16) float Qs[DD][QSTRIDE];   // [d][l], transposed
    __shared__ __align__(16) float KVs[DD][MM];
    __shared__ float ksums[DD];
    __shared__ float zs[LTILE];

    for (int idx = tid; idx < LTILE * DD; idx += 128) {
        const int l = idx >> 6, d = idx & 63;
        Qs[d][l] = phi(Qg[((n * LQ + l0 + l) * 8 + h) * DD + d]);
    }
    for (int idx = tid; idx < DD * MM / 4; idx += 128)
        ((float4*)KVs)[idx] = ((const float4*)(g_KV + nh * DD * MM))[idx];
    if (tid < DD) ksums[tid] = g_Ksum[nh * DD + tid];
    __syncthreads();

    if (tid < LTILE) {
        float a = 0.f;
        #pragma unroll
        for (int d = 0; d < DD; d++) a = fmaf(Qs[d][tid], ksums[d], a);
        zs[tid] = 1.f / (a + 1e-6f);
    }
    __syncthreads();

    ull acc[4][4];
    #pragma unroll
    for (int i = 0; i < 4; i++)
        #pragma unroll
        for (int j = 0; j < 4; j++) acc[i][j] = 0ull;

    #pragma unroll 4
    for (int d = 0; d < DD; d++) {
        F4U q4, ka, kb;
        q4.f = *(const float4*)&Qs[d][4 * tl];
        ka.f = ((const float4*)&KVs[d][0])[2 * tm];
        kb.f = ((const float4*)&KVs[d][0])[2 * tm + 1];
        #pragma unroll
        for (int i = 0; i < 4; i++) {
            const ull qq = pack2(q4.s[i], q4.s[i]);
            ffma2(acc[i][0], qq, ka.u[0]);
            ffma2(acc[i][1], qq, ka.u[1]);
            ffma2(acc[i][2], qq, kb.u[0]);
            ffma2(acc[i][3], qq, kb.u[1]);
        }
    }

    #pragma unroll
    for (int i = 0; i < 4; i++) {
        const int l = l0 + 4 * tl + i;
        const float z = zs[4 * tl + i];
        const ull zz = pack2(z, z);
        F4U lo, hi;
        lo.u[0] = mul2(acc[i][0], zz); lo.u[1] = mul2(acc[i][1], zz);
        hi.u[0] = mul2(acc[i][2], zz); hi.u[1] = mul2(acc[i][3], zz);
        float* o = Outg + ((n * LQ + l) * 8 + h) * MM + 8 * tm;
        *(float4*)o       = lo.f;
        *(float4*)(o + 4) = hi.f;
    }
}

extern "C" void kernel_launch(void* const* d_in, const int* in_sizes, int n_in,
                              void* d_out, int out_size)
{
    const float* Q    = (const float*)d_in[0];
    const float* K    = (const float*)d_in[1];
    const float* V    = (const float*)d_in[2];
    const float* mask = (const float*)d_in[3];
    float* Out = (float*)d_out;

    stage1_kernel<<<dim3(NH_TOT, S1_CHUNKS), 128>>>(K, V, mask);
    reduce_kernel<<<260, 256>>>();
    stage2_kernel<<<dim3(LQ / LTILE, NH_TOT), 128>>>(Q, Out);
}